// round 16
// baseline (speedup 1.0000x reference)
#include <cuda_runtime.h>
#include <cuda_bf16.h>

// RAM multi-step transformer — R13/R14 structure (27.1us baseline) with the
// u16-packed conn tables stored TRANSPOSED (lane-major): for each phase
// round, a warp's 32 threads read CONSECUTIVE int4s -> 4 wavefronts per
// LDG.128 instead of 8 (neuron-major). L1tex wavefront pipe is co-binding
// (R13 vs R15 evidence), so conn wavefronts are worth halving again.
//
// x: (256,1024) i32 | conn_in: (2048,16) | conn_state: (1024,16) | conn_out: (512,16)
// mem_in: (2048,65536) f32 | mem_state: (1024,65536) f32 | mem_out: (512,65536) f32
// out: (256,512) f32

#define BATCH 256
#define IN_BITS 1024
#define N_IN 2048
#define N_ST 1024
#define N_OUT 512
#define TBL 65536
#define MAX_ITERS 4
#define THREADS 256

// Transposed u16-packed conn, int4-granular.
// int4 units: in = [0,4096): (r*2+q)*256+tid ; state = [4096,6144):
// 4096+(k*2+q)*256+tid ; out = [6144,7168): 6144+(r*2+q)*256+tid.
// Each int4 = 8 u32 words? No: 4 u32 words, each = (lo u16 | hi u16<<16),
// word j of the neuron's pair q covers source indices (q*4+s)*2, +1.
#define G4_IN 0
#define G4_ST 4096
#define G4_OUT 6144
#define G4_TOT 7168
#define GW_TOT (G4_TOT * 4)        // 28672 u32 words

__device__ unsigned g_conn16[GW_TOT];

__global__ void pack_conn(const int* __restrict__ ci,
                          const int* __restrict__ cs,
                          const int* __restrict__ co) {
    int u = blockIdx.x * blockDim.x + threadIdx.x;   // u32 word index
    if (u >= GW_TOT) return;
    const int* src;
    int v, rows;                                      // rows = rounds*2
    if (u < G4_ST * 4)       { src = ci; v = u;              rows = 16; }
    else if (u < G4_OUT * 4) { src = cs; v = u - G4_ST * 4;  rows = 8;  }
    else                     { src = co; v = u - G4_OUT * 4; rows = 4;  }
    int s   = v & 3;            // u32 within int4
    int i4  = v >> 2;
    int col = i4 % 256;         // tid
    int row = i4 / 256;         // 0..rows-1
    int rr  = row >> 1;         // round
    int q   = row & 1;          // int4 pair half
    int n   = rr * 256 + col;   // neuron
    int j   = q * 4 + s;        // u32 word within neuron (0..7)
    (void)rows;
    unsigned lo = (unsigned)src[n * 16 + 2 * j];
    unsigned hi = (unsigned)src[n * 16 + 2 * j + 1];
    g_conn16[u] = (lo & 0xFFFFu) | (hi << 16);
}

__device__ __forceinline__ unsigned long long mk_policy_pin() {
    unsigned long long pol;
    asm("createpolicy.fractional.L2::evict_last.b64 %0, 1.0;" : "=l"(pol));
    return pol;
}
__device__ __forceinline__ unsigned long long mk_policy_state() {
    unsigned long long pol;
    asm("createpolicy.fractional.L2::evict_last.L2::evict_first.b64 %0, 0.25;" : "=l"(pol));
    return pol;
}
__device__ __forceinline__ float ld_tbl64(const float* p, unsigned long long pol) {
    float v;
    asm("ld.global.nc.L2::cache_hint.L2::64B.f32 %0, [%1], %2;"
        : "=f"(v) : "l"(p), "l"(pol));
    return v;
}

__device__ __forceinline__ unsigned bitw(const unsigned* __restrict__ sw, unsigned idx) {
    return (sw[idx >> 5] >> (idx & 31)) & 1u;
}

// 16-bit address from two int4s holding 16 packed u16 indices.
__device__ __forceinline__ unsigned gather16pk(const unsigned* __restrict__ sw,
                                               int4 A, int4 B) {
    unsigned a = 0, w;
    w = (unsigned)A.x; a |= bitw(sw, w & 0xFFFFu) << 0;  a |= bitw(sw, w >> 16) << 1;
    w = (unsigned)A.y; a |= bitw(sw, w & 0xFFFFu) << 2;  a |= bitw(sw, w >> 16) << 3;
    w = (unsigned)A.z; a |= bitw(sw, w & 0xFFFFu) << 4;  a |= bitw(sw, w >> 16) << 5;
    w = (unsigned)A.w; a |= bitw(sw, w & 0xFFFFu) << 6;  a |= bitw(sw, w >> 16) << 7;
    w = (unsigned)B.x; a |= bitw(sw, w & 0xFFFFu) << 8;  a |= bitw(sw, w >> 16) << 9;
    w = (unsigned)B.y; a |= bitw(sw, w & 0xFFFFu) << 10; a |= bitw(sw, w >> 16) << 11;
    w = (unsigned)B.z; a |= bitw(sw, w & 0xFFFFu) << 12; a |= bitw(sw, w >> 16) << 13;
    w = (unsigned)B.w; a |= bitw(sw, w & 0xFFFFu) << 14; a |= bitw(sw, w >> 16) << 15;
    return a;
}

__global__ __launch_bounds__(THREADS, 2)
void ram_multistep_kernel(
    const int* __restrict__ x,
    const float* __restrict__ mem_in,
    const float* __restrict__ mem_state,
    const float* __restrict__ mem_out,
    float* __restrict__ out)
{
    __shared__ unsigned sx[32];       // 1024 input bits packed
    __shared__ unsigned sbufA[96];    // [0,64) in-bits, [64,96) state bits
    __shared__ unsigned sbufB[96];    // double buffer

    const int b = blockIdx.x;
    const int tid = threadIdx.x;
    const int lane = tid & 31;
    const int warp = tid >> 5;        // 0..7

    const int4* g4 = (const int4*)g_conn16;

    const unsigned long long pol_pin   = mk_policy_pin();
    const unsigned long long pol_state = mk_policy_state();

    // ---- Pack x bits (coalesced, ballot) ----
    #pragma unroll
    for (int r = 0; r < 4; r++) {
        int bit = __ldg(x + b * IN_BITS + r * 256 + tid);
        unsigned w = __ballot_sync(0xFFFFFFFFu, bit != 0);
        if (lane == 0) sx[r * 8 + warp] = w;
    }
    if (tid < 32) sbufA[64 + tid] = 0u;    // initial state = 0 (read by iter 0)
    __syncthreads();

    // ---- Hoist transposed state conn: coalesced, overlaps in-phase, reused x4 ----
    int4 cs[8];
    #pragma unroll
    for (int k = 0; k < 4; k++) {
        cs[2 * k]     = __ldg(g4 + G4_ST + (k * 2 + 0) * 256 + tid);
        cs[2 * k + 1] = __ldg(g4 + G4_ST + (k * 2 + 1) * 256 + tid);
    }

    // ---- Input layer: 2048 neurons, 8 per thread, transposed u16 conn ----
    {
        unsigned addr[8];
        #pragma unroll
        for (int r = 0; r < 8; r++) {
            int4 A = __ldg(g4 + G4_IN + (r * 2 + 0) * 256 + tid);
            int4 B = __ldg(g4 + G4_IN + (r * 2 + 1) * 256 + tid);
            addr[r] = gather16pk(sx, A, B);
        }
        float v[8];
        #pragma unroll
        for (int r = 0; r < 8; r++) {
            int n = r * 256 + tid;
            v[r] = ld_tbl64(mem_in + (size_t)n * TBL + addr[r], pol_pin);
        }
        #pragma unroll
        for (int r = 0; r < 8; r++) {
            unsigned w = __ballot_sync(0xFFFFFFFFu, v[r] > 0.5f);
            if (lane == 0) { sbufA[r * 8 + warp] = w; sbufB[r * 8 + warp] = w; }
        }
    }

    // ---- Hoist transposed out conn before the state loop ----
    int4 co[4];
    #pragma unroll
    for (int r = 0; r < 2; r++) {
        co[2 * r]     = __ldg(g4 + G4_OUT + (r * 2 + 0) * 256 + tid);
        co[2 * r + 1] = __ldg(g4 + G4_OUT + (r * 2 + 1) * 256 + tid);
    }
    __syncthreads();

    // ---- Recurrent state iterations: 4 per thread, 1 barrier/iter ----
    unsigned* cur = sbufA;
    unsigned* nxt = sbufB;
    for (int it = 0; it < MAX_ITERS; it++) {
        unsigned addr[4];
        #pragma unroll
        for (int k = 0; k < 4; k++)
            addr[k] = gather16pk(cur, cs[2 * k], cs[2 * k + 1]);
        float v[4];
        #pragma unroll
        for (int k = 0; k < 4; k++) {
            int n = k * 256 + tid;
            v[k] = ld_tbl64(mem_state + (size_t)n * TBL + addr[k], pol_state);
        }
        #pragma unroll
        for (int k = 0; k < 4; k++) {
            unsigned w = __ballot_sync(0xFFFFFFFFu, v[k] > 0.5f);
            if (lane == 0) nxt[64 + k * 8 + warp] = w;   // disjoint from cur
        }
        __syncthreads();                 // nxt complete & visible
        unsigned* t = cur; cur = nxt; nxt = t;
    }

    // ---- Output layer: 512 neurons, 2 per thread (final state only) ----
    {
        unsigned addr[2];
        #pragma unroll
        for (int r = 0; r < 2; r++)
            addr[r] = gather16pk(cur, co[2 * r], co[2 * r + 1]);
        #pragma unroll
        for (int r = 0; r < 2; r++) {
            int n = r * 256 + tid;
            out[b * N_OUT + n] = ld_tbl64(mem_out + (size_t)n * TBL + addr[r], pol_pin);
        }
    }
}

extern "C" void kernel_launch(void* const* d_in, const int* in_sizes, int n_in,
                              void* d_out, int out_size) {
    const int* x            = (const int*)d_in[0];
    const int* conn_in      = (const int*)d_in[1];
    const int* conn_state   = (const int*)d_in[2];
    const int* conn_out     = (const int*)d_in[3];
    const float* mem_in     = (const float*)d_in[4];
    const float* mem_state  = (const float*)d_in[5];
    const float* mem_out    = (const float*)d_in[6];
    float* out = (float*)d_out;

    pack_conn<<<(GW_TOT + 255) / 256, 256>>>(conn_in, conn_state, conn_out);
    ram_multistep_kernel<<<BATCH, THREADS>>>(x, mem_in, mem_state, mem_out, out);
}

// round 17
// speedup vs baseline: 1.1860x; 1.1860x over previous
#include <cuda_runtime.h>
#include <cuda_bf16.h>

// RAM multi-step transformer — best-known configuration (R13/R14, 27.1us):
//  * pre-kernel packs conn tables i32->u16, NEURON-MAJOR (R16 transpose regressed)
//  * state conn (32 regs) + out conn (16 regs) hoisted, reused across iters
//  * L2::64B fills on all table loads; evict_last in/out, fractional state
//  * in-phase interleaves conn-load/gather/table-issue (earlier first miss),
//    ballots batched after all loads (full MLP=8 preserved)
//
// x: (256,1024) i32 | conn_in: (2048,16) | conn_state: (1024,16) | conn_out: (512,16)
// mem_in: (2048,65536) f32 | mem_state: (1024,65536) f32 | mem_out: (512,65536) f32
// out: (256,512) f32

#define BATCH 256
#define IN_BITS 1024
#define N_IN 2048
#define N_ST 1024
#define N_OUT 512
#define TBL 65536
#define MAX_ITERS 4
#define THREADS 256

#define C16_IN 0
#define C16_ST (N_IN * 16)                  // 32768
#define C16_OUT (C16_ST + N_ST * 16)        // 49152
#define C16_TOT (C16_OUT + N_OUT * 16)      // 57344

__device__ unsigned short g_conn16[C16_TOT];

__global__ void pack_conn(const int* __restrict__ ci,
                          const int* __restrict__ cs,
                          const int* __restrict__ co) {
    int i = blockIdx.x * blockDim.x + threadIdx.x;
    if (i < C16_ST)       g_conn16[i] = (unsigned short)ci[i];
    else if (i < C16_OUT) g_conn16[i] = (unsigned short)cs[i - C16_ST];
    else if (i < C16_TOT) g_conn16[i] = (unsigned short)co[i - C16_OUT];
}

__device__ __forceinline__ unsigned long long mk_policy_pin() {
    unsigned long long pol;
    asm("createpolicy.fractional.L2::evict_last.b64 %0, 1.0;" : "=l"(pol));
    return pol;
}
__device__ __forceinline__ unsigned long long mk_policy_state() {
    unsigned long long pol;
    asm("createpolicy.fractional.L2::evict_last.L2::evict_first.b64 %0, 0.25;" : "=l"(pol));
    return pol;
}
__device__ __forceinline__ float ld_tbl64(const float* p, unsigned long long pol) {
    float v;
    asm("ld.global.nc.L2::cache_hint.L2::64B.f32 %0, [%1], %2;"
        : "=f"(v) : "l"(p), "l"(pol));
    return v;
}

__device__ __forceinline__ unsigned bitw(const unsigned* __restrict__ sw, unsigned idx) {
    return (sw[idx >> 5] >> (idx & 31)) & 1u;
}

// 16-bit address from two int4s holding 16 packed u16 indices.
__device__ __forceinline__ unsigned gather16pk(const unsigned* __restrict__ sw,
                                               int4 A, int4 B) {
    unsigned a = 0, w;
    w = (unsigned)A.x; a |= bitw(sw, w & 0xFFFFu) << 0;  a |= bitw(sw, w >> 16) << 1;
    w = (unsigned)A.y; a |= bitw(sw, w & 0xFFFFu) << 2;  a |= bitw(sw, w >> 16) << 3;
    w = (unsigned)A.z; a |= bitw(sw, w & 0xFFFFu) << 4;  a |= bitw(sw, w >> 16) << 5;
    w = (unsigned)A.w; a |= bitw(sw, w & 0xFFFFu) << 6;  a |= bitw(sw, w >> 16) << 7;
    w = (unsigned)B.x; a |= bitw(sw, w & 0xFFFFu) << 8;  a |= bitw(sw, w >> 16) << 9;
    w = (unsigned)B.y; a |= bitw(sw, w & 0xFFFFu) << 10; a |= bitw(sw, w >> 16) << 11;
    w = (unsigned)B.z; a |= bitw(sw, w & 0xFFFFu) << 12; a |= bitw(sw, w >> 16) << 13;
    w = (unsigned)B.w; a |= bitw(sw, w & 0xFFFFu) << 14; a |= bitw(sw, w >> 16) << 15;
    return a;
}

__global__ __launch_bounds__(THREADS, 2)
void ram_multistep_kernel(
    const int* __restrict__ x,
    const float* __restrict__ mem_in,
    const float* __restrict__ mem_state,
    const float* __restrict__ mem_out,
    float* __restrict__ out)
{
    __shared__ unsigned sx[32];       // 1024 input bits packed
    __shared__ unsigned sbufA[96];    // [0,64) in-bits, [64,96) state bits
    __shared__ unsigned sbufB[96];    // double buffer

    const int b = blockIdx.x;
    const int tid = threadIdx.x;
    const int lane = tid & 31;
    const int warp = tid >> 5;        // 0..7

    const unsigned long long pol_pin   = mk_policy_pin();
    const unsigned long long pol_state = mk_policy_state();

    // ---- Pack x bits (coalesced, ballot) ----
    #pragma unroll
    for (int r = 0; r < 4; r++) {
        int bit = __ldg(x + b * IN_BITS + r * 256 + tid);
        unsigned w = __ballot_sync(0xFFFFFFFFu, bit != 0);
        if (lane == 0) sx[r * 8 + warp] = w;
    }
    if (tid < 32) sbufA[64 + tid] = 0u;    // initial state = 0 (read by iter 0)
    __syncthreads();

    // ---- Hoist packed state conn: overlaps in-phase, reused across 4 iters ----
    int4 cs[8];                            // 4 neurons x 2 int4 (16 u16 each)
    #pragma unroll
    for (int k = 0; k < 4; k++) {
        const int4* cp = (const int4*)(g_conn16 + C16_ST + (size_t)(k * 256 + tid) * 16);
        cs[2 * k]     = __ldg(cp);
        cs[2 * k + 1] = __ldg(cp + 1);
    }

    // ---- Input layer: 2048 neurons, 8 per thread; interleaved issue ----
    {
        float v[8];
        #pragma unroll
        for (int r = 0; r < 8; r++) {
            const int4* cp = (const int4*)(g_conn16 + C16_IN + (size_t)(r * 256 + tid) * 16);
            int4 A = __ldg(cp), B = __ldg(cp + 1);
            unsigned addr = gather16pk(sx, A, B);
            int n = r * 256 + tid;
            v[r] = ld_tbl64(mem_in + (size_t)n * TBL + addr, pol_pin);
        }
        #pragma unroll
        for (int r = 0; r < 8; r++) {
            unsigned w = __ballot_sync(0xFFFFFFFFu, v[r] > 0.5f);
            if (lane == 0) { sbufA[r * 8 + warp] = w; sbufB[r * 8 + warp] = w; }
        }
    }

    // ---- Hoist packed out conn before the state loop ----
    int4 co[4];                            // 2 neurons x 2 int4
    #pragma unroll
    for (int r = 0; r < 2; r++) {
        const int4* cp = (const int4*)(g_conn16 + C16_OUT + (size_t)(r * 256 + tid) * 16);
        co[2 * r]     = __ldg(cp);
        co[2 * r + 1] = __ldg(cp + 1);
    }
    __syncthreads();

    // ---- Recurrent state iterations: 4 per thread, 1 barrier/iter ----
    unsigned* cur = sbufA;
    unsigned* nxt = sbufB;
    for (int it = 0; it < MAX_ITERS; it++) {
        unsigned addr[4];
        #pragma unroll
        for (int k = 0; k < 4; k++)
            addr[k] = gather16pk(cur, cs[2 * k], cs[2 * k + 1]);
        float v[4];
        #pragma unroll
        for (int k = 0; k < 4; k++) {
            int n = k * 256 + tid;
            v[k] = ld_tbl64(mem_state + (size_t)n * TBL + addr[k], pol_state);
        }
        #pragma unroll
        for (int k = 0; k < 4; k++) {
            unsigned w = __ballot_sync(0xFFFFFFFFu, v[k] > 0.5f);
            if (lane == 0) nxt[64 + k * 8 + warp] = w;   // disjoint from cur
        }
        __syncthreads();                 // nxt complete & visible
        unsigned* t = cur; cur = nxt; nxt = t;
    }

    // ---- Output layer: 512 neurons, 2 per thread (final state only) ----
    {
        unsigned addr[2];
        #pragma unroll
        for (int r = 0; r < 2; r++)
            addr[r] = gather16pk(cur, co[2 * r], co[2 * r + 1]);
        #pragma unroll
        for (int r = 0; r < 2; r++) {
            int n = r * 256 + tid;
            out[b * N_OUT + n] = ld_tbl64(mem_out + (size_t)n * TBL + addr[r], pol_pin);
        }
    }
}

extern "C" void kernel_launch(void* const* d_in, const int* in_sizes, int n_in,
                              void* d_out, int out_size) {
    const int* x            = (const int*)d_in[0];
    const int* conn_in      = (const int*)d_in[1];
    const int* conn_state   = (const int*)d_in[2];
    const int* conn_out     = (const int*)d_in[3];
    const float* mem_in     = (const float*)d_in[4];
    const float* mem_state  = (const float*)d_in[5];
    const float* mem_out    = (const float*)d_in[6];
    float* out = (float*)d_out;

    pack_conn<<<(C16_TOT + 255) / 256, 256>>>(conn_in, conn_state, conn_out);
    ram_multistep_kernel<<<BATCH, THREADS>>>(x, mem_in, mem_state, mem_out, out);
}